// round 6
// baseline (speedup 1.0000x reference)
#include <cuda_runtime.h>
#include <float.h>

// Scratch for per-sample CE losses (allocation-free: __device__ global).
__device__ float g_ce[32768];

// ---------------------------------------------------------------------------
// Kernel 1: per-row cross entropy + inline target-dtype detection.
// One warp per row, row (C<=1024 floats) held in registers. ~HBM-bound.
// ---------------------------------------------------------------------------
__global__ void __launch_bounds__(256)
ce_kernel(const float* __restrict__ x,
          const void* __restrict__ tgt,
          int N, int C)
{
    const int row  = blockIdx.x * 8 + (threadIdx.x >> 5);
    const int lane = threadIdx.x & 31;
    if (row >= N) return;

    const float4* rp = reinterpret_cast<const float4*>(x + (size_t)row * C);
    const int C4 = C >> 2;  // 250 for C=1000

    float4 v[8];
#pragma unroll
    for (int i = 0; i < 8; i++) {
        int c = lane + (i << 5);
        if (c < C4) v[i] = rp[c];
        else        v[i] = make_float4(-FLT_MAX, -FLT_MAX, -FLT_MAX, -FLT_MAX);
    }

    // Dtype probe (int64 targets in [0,C) have zero odd words; L1-hot).
    const int* tw = reinterpret_cast<const int*>(tgt);
    int hiw = tw[2 * lane + 1];
    bool is64 = __all_sync(0xFFFFFFFFu, hiw == 0);

    float xt = 0.f;
    if (lane == 0) {
        long long t = is64 ? reinterpret_cast<const long long*>(tgt)[row]
                           : (long long)reinterpret_cast<const int*>(tgt)[row];
        if (t < 0)  t = 0;
        if (t >= C) t = C - 1;
        xt = x[(size_t)row * C + (int)t];
    }

    float m = -FLT_MAX;
#pragma unroll
    for (int i = 0; i < 8; i++)
        m = fmaxf(m, fmaxf(fmaxf(v[i].x, v[i].y), fmaxf(v[i].z, v[i].w)));
#pragma unroll
    for (int o = 16; o; o >>= 1)
        m = fmaxf(m, __shfl_xor_sync(0xFFFFFFFFu, m, o));

    float s0 = 0.f, s1 = 0.f, s2 = 0.f, s3 = 0.f;
#pragma unroll
    for (int i = 0; i < 8; i++) {
        s0 += __expf(v[i].x - m);
        s1 += __expf(v[i].y - m);
        s2 += __expf(v[i].z - m);
        s3 += __expf(v[i].w - m);
    }
    float s = (s0 + s1) + (s2 + s3);
#pragma unroll
    for (int o = 16; o; o >>= 1)
        s += __shfl_xor_sync(0xFFFFFFFFu, s, o);

    if (lane == 0)
        g_ce[row] = m + __logf(s) - xt;
}

// ---------------------------------------------------------------------------
// Kernel 2: single CTA, 1024 threads x 32 values.
// Keys bit-transposed in registers (32x32 HD transpose): m[idx] holds key-bit
// (31-idx) across the thread's 32 slots (slot s at bit position (31-s)).
// Exact rank-k select via 16-way (4-bit) MSB-first radix: 8 rounds, only
// 2 __syncthreads per round (vs 64 total before).
// ---------------------------------------------------------------------------
__global__ void __launch_bounds__(1024)
select_mean_kernel(float* __restrict__ out, int N, int k)
{
    const int tid  = threadIdx.x;
    const int lane = tid & 31;
    const int wid  = tid >> 5;

    // Load keys (order-preserving uint transform of float bits).
    unsigned m[32];
#pragma unroll
    for (int i = 0; i < 32; i++) {
        int idx = tid + (i << 10);
        unsigned b = (idx < N) ? __float_as_uint(g_ce[idx]) : 0xFF800000u; // -inf pad
        m[i] = (b & 0x80000000u) ? ~b : (b | 0x80000000u);
    }

    // In-place 32x32 bit transpose (Hacker's Delight).
#pragma unroll
    for (int st = 0; st < 5; st++) {
        const int j = 16 >> st;
        const unsigned msk = (st == 0) ? 0x0000FFFFu :
                             (st == 1) ? 0x00FF00FFu :
                             (st == 2) ? 0x0F0F0F0Fu :
                             (st == 3) ? 0x33333333u : 0x55555555u;
#pragma unroll
        for (int kk = 0; kk < 32; kk++) {
            if ((kk & j) == 0) {
                unsigned t2 = (m[kk] ^ (m[kk + j] >> j)) & msk;
                m[kk]     ^= t2;
                m[kk + j] ^= (t2 << j);
            }
        }
    }

    __shared__ int   s_cnt[16 * 32];   // [bucket][warp]
    __shared__ int   s_sel;
    __shared__ float s_fsum[32];

    unsigned amask  = 0xFFFFFFFFu;  // active slots (slot s <-> bit 31-s)
    unsigned lamkey = 0u;
    int rank = k;                   // consumed by tid 0 only

    // 8 rounds x 4 bits, MSB first. Round r uses planes m[4r..4r+3].
#pragma unroll
    for (int r = 0; r < 8; r++) {
        const unsigned p0 = m[4 * r + 0];
        const unsigned p1 = m[4 * r + 1];
        const unsigned p2 = m[4 * r + 2];
        const unsigned p3 = m[4 * r + 3];

        // Bucket counts: j's bits (3..0) = required values of p0..p3.
#pragma unroll
        for (int j = 0; j < 16; j++) {
            unsigned sel = amask;
            sel &= (j & 8) ? p0 : ~p0;
            sel &= (j & 4) ? p1 : ~p1;
            sel &= (j & 2) ? p2 : ~p2;
            sel &= (j & 1) ? p3 : ~p3;
            int c = __reduce_add_sync(0xFFFFFFFFu, __popc(sel));
            if (lane == j) s_cnt[j * 32 + wid] = c;
        }
        __syncthreads();

        // Warp 0: reduce each bucket across warps, then lane 0 scans 15..0.
        if (wid == 0) {
            int bc[16];
#pragma unroll
            for (int j = 0; j < 16; j++)
                bc[j] = __reduce_add_sync(0xFFFFFFFFu, s_cnt[j * 32 + lane]);
            if (lane == 0) {
                int chosen = 0;
                bool found = false;
#pragma unroll
                for (int t = 15; t >= 1; t--) {
                    if (!found) {
                        if (rank < bc[t]) { chosen = t; found = true; }
                        else               rank -= bc[t];
                    }
                }
                s_sel = chosen;
            }
        }
        __syncthreads();

        const int j = s_sel;
        unsigned sel = amask;
        sel &= (j & 8) ? p0 : ~p0;
        sel &= (j & 4) ? p1 : ~p1;
        sel &= (j & 2) ? p2 : ~p2;
        sel &= (j & 1) ? p3 : ~p3;
        amask = sel;
        lamkey |= ((unsigned)j) << (28 - 4 * r);
        __syncthreads();  // protect s_cnt / s_sel reuse next round
    }

    // ge mask: slots with key >= lamkey (exact tie semantics of sorted_desc[k]).
    unsigned eq = 0xFFFFFFFFu, gt = 0u;
#pragma unroll
    for (int idx = 0; idx < 32; idx++) {
        if ((lamkey >> (31 - idx)) & 1u) {
            eq &= m[idx];
        } else {
            gt |= eq & m[idx];
            eq &= ~m[idx];
        }
    }
    const unsigned ge = gt | eq;

    // Masked sum of kept losses (g_ce is L2-resident), then mean over N.
    float sum = 0.f;
#pragma unroll
    for (int i = 0; i < 32; i++) {
        int idx = tid + (i << 10);
        if (((ge >> (31 - i)) & 1u) && idx < N)
            sum += g_ce[idx];
    }
#pragma unroll
    for (int o = 16; o; o >>= 1)
        sum += __shfl_xor_sync(0xFFFFFFFFu, sum, o);
    if (lane == 0) s_fsum[wid] = sum;
    __syncthreads();

    if (tid == 0) {
        double tot = 0.0;
#pragma unroll
        for (int w = 0; w < 32; w++) tot += (double)s_fsum[w];
        out[0] = (float)(tot / (double)N);
    }
}

// ---------------------------------------------------------------------------
extern "C" void kernel_launch(void* const* d_in, const int* in_sizes, int n_in,
                              void* d_out, int out_size)
{
    int li = 0, ti = 1;
    if (n_in >= 2 && in_sizes[1] > in_sizes[0]) { li = 1; ti = 0; }

    const float* x   = (const float*)d_in[li];
    const void*  tgt = d_in[ti];
    float* out = (float*)d_out;

    const int N = in_sizes[ti];            // 32768
    const int C = in_sizes[li] / N;        // 1000
    const int k = (int)((double)N * 0.3);  // 9830

    const int warps_per_block = 8;
    const int blocks = (N + warps_per_block - 1) / warps_per_block;
    ce_kernel<<<blocks, 256>>>(x, tgt, N, C);

    select_mean_kernel<<<1, 1024>>>(out, N, k);
}